// round 4
// baseline (speedup 1.0000x reference)
#include <cuda_runtime.h>
#include <math.h>

// Problem constants
#define H     1536
#define H3    4608          // 3*H
#define HV    128           // vocab
#define ML    128           // max_length
#define AROWS 129           // ML+1 attention rows
#define GRID  148
#define BLOCK 1024

// ---------------- device scratch (no allocations allowed) ----------------
__device__ __align__(16) float g_h[2][H];            // ping-pong hidden state
__device__ __align__(16) float g_encout[AROWS * H];  // encoder_outputs (129 x 1536)
__device__ __align__(16) float g_gh[H3];             // dec_Whh @ h + bhh
__device__ __align__(16) float g_attnlog[AROWS];     // attention logits
__device__ __align__(16) float g_ctx[H];             // attention context
__device__ __align__(16) float g_x[H];               // relu(comb) input to dec GRU
__device__ __align__(16) float g_o[HV];              // output logits (pre log-softmax)
__device__ unsigned g_bar;                           // grid barrier (monotonic)

// ---------------- grid-wide barrier (all 148 CTAs resident: 1 CTA/SM) ----
__device__ __forceinline__ void grid_sync() {
    __syncthreads();
    if (threadIdx.x == 0) {
        __threadfence();
        unsigned nb  = gridDim.x;
        unsigned old = atomicAdd(&g_bar, 1u);
        unsigned target = old - (old % nb) + nb;   // next multiple of nb
        while ((int)(*(volatile unsigned*)&g_bar - target) < 0) { }
        __threadfence();
    }
    __syncthreads();
}

// ---------------- warp helpers ----------------
__device__ __forceinline__ float wredu(float v) {
#pragma unroll
    for (int o = 16; o; o >>= 1) v += __shfl_xor_sync(0xffffffffu, v, o);
    return v;
}

// partial (per-lane) dot of a 1536-length row with a 1536-length vector
__device__ __forceinline__ float dot1536(const float* __restrict__ w,
                                         const float* __restrict__ x, int lane) {
    const float4* w4 = (const float4*)w;
    const float4* x4 = (const float4*)x;
    float s = 0.f;
#pragma unroll 4
    for (int i = 0; i < 12; i++) {
        float4 a = w4[lane + 32 * i];
        float4 b = x4[lane + 32 * i];
        s = fmaf(a.x, b.x, s);
        s = fmaf(a.y, b.y, s);
        s = fmaf(a.z, b.z, s);
        s = fmaf(a.w, b.w, s);
    }
    return s;
}

__device__ __forceinline__ float sigm(float x) { return 1.f / (1.f + expf(-x)); }

// ---------------- persistent kernel ----------------
__global__ __launch_bounds__(BLOCK, 1)
void seq2seq_kernel(const int* __restrict__ input, int L,
                    const float* __restrict__ emb_enc,
                    const float* __restrict__ enc_Wih, const float* __restrict__ enc_Whh,
                    const float* __restrict__ enc_bih, const float* __restrict__ enc_bhh,
                    const float* __restrict__ emb_dec,
                    const float* __restrict__ attn_W, const float* __restrict__ attn_b,
                    const float* __restrict__ comb_W, const float* __restrict__ comb_b,
                    const float* __restrict__ dec_Wih, const float* __restrict__ dec_Whh,
                    const float* __restrict__ dec_bih, const float* __restrict__ dec_bhh,
                    const float* __restrict__ out_W, const float* __restrict__ out_b,
                    float* __restrict__ out, int write_tok)
{
    const int tid  = threadIdx.x;
    const int lane = tid & 31;
    const int wid  = tid >> 5;
    // interleave warp ids across blocks so every phase keeps all SMs busy
    const int WGID = wid * gridDim.x + blockIdx.x;
    const int NW   = gridDim.x * (blockDim.x >> 5);

    __shared__ float s_w[AROWS];
    __shared__ float s_ps[8 * 128];
    __shared__ float s_m, s_s, s_lse;
    __shared__ int   s_tok;

    // ---- init: zero h0 and the unused tail rows of encoder_outputs ----
    {
        int gt = blockIdx.x * blockDim.x + tid;
        int NT = gridDim.x * blockDim.x;
        for (int i = gt; i < H; i += NT) g_h[0][i] = 0.f;
        for (int i = L * H + gt; i < AROWS * H; i += NT) g_encout[i] = 0.f;
    }
    grid_sync();

    int cur = 0;

    // =========================== ENCODER ===========================
    for (int t = 0; t < L; t++) {
        const float* x    = emb_enc + input[t] * H;
        const float* hold = g_h[cur];
        float*       hnew = g_h[cur ^ 1];

        for (int j = WGID; j < H; j += NW) {
            float ar = dot1536(enc_Wih + j * H,            x, lane);
            float az = dot1536(enc_Wih + (H + j) * H,      x, lane);
            float an = dot1536(enc_Wih + (2 * H + j) * H,  x, lane);
            float br = dot1536(enc_Whh + j * H,            hold, lane);
            float bz = dot1536(enc_Whh + (H + j) * H,      hold, lane);
            float bn = dot1536(enc_Whh + (2 * H + j) * H,  hold, lane);
            float rp  = wredu(ar + br);
            float zp  = wredu(az + bz);
            float anr = wredu(an);
            float bnr = wredu(bn);
            if (lane == 0) {
                float r  = sigm(rp + enc_bih[j] + enc_bhh[j]);
                float z  = sigm(zp + enc_bih[H + j] + enc_bhh[H + j]);
                float n  = tanhf(anr + enc_bih[2 * H + j] + r * (bnr + enc_bhh[2 * H + j]));
                float hv = (1.f - z) * n + z * hold[j];
                hnew[j] = hv;
                g_encout[t * H + j] = hv;
            }
        }
        grid_sync();
        cur ^= 1;
    }

    // =========================== DECODER ===========================
    for (int t = 0; t < ML; t++) {
        // --- token selection (redundant per block, deterministic) + emit row t-1 ---
        if (tid == 0) {
            if (t == 0) {
                s_tok = 0; s_lse = 0.f;   // SOS
            } else {
                float m = -1e30f; int am = 0;
                for (int v = 0; v < HV; v++) {
                    float ov = g_o[v];
                    if (ov > m) { m = ov; am = v; }
                }
                float s = 0.f;
                for (int v = 0; v < HV; v++) s += expf(g_o[v] - m);
                s_lse = m + logf(s);
                s_tok = am;
            }
        }
        __syncthreads();
        const int tok = s_tok;
        if (t > 0 && blockIdx.x == 0) {
            if (tid < HV) out[(t - 1) * HV + tid] = g_o[tid] - s_lse;
            if (tid == HV && write_tok) out[ML * HV + (t - 1)] = (float)tok;
        }

        const float* emb  = emb_dec + tok * H;
        const float* hold = g_h[cur];

        // --- D1: attention logits (129 rows) || dec_Whh @ h + bhh (4608 rows) ---
        for (int task = WGID; task < AROWS + H3; task += NW) {
            if (task < AROWS) {
                const float* w = attn_W + task * (2 * H);
                float s = dot1536(w, emb, lane) + dot1536(w + H, hold, lane);
                s = wredu(s);
                if (lane == 0) g_attnlog[task] = s + attn_b[task];
            } else {
                int r = task - AROWS;
                float s = wredu(dot1536(dec_Whh + r * H, hold, lane));
                if (lane == 0) g_gh[r] = s + dec_bhh[r];
            }
        }
        grid_sync();

        // --- D2: softmax (per ctx-block) + context = w @ encoder_outputs ---
        if (blockIdx.x < 12) {
            if (tid == 0) {
                float m = -1e30f;
                for (int i = 0; i < AROWS; i++) m = fmaxf(m, g_attnlog[i]);
                float s = 0.f;
                for (int i = 0; i < AROWS; i++) s += expf(g_attnlog[i] - m);
                s_m = m; s_s = s;
            }
            __syncthreads();
            if (tid < AROWS) s_w[tid] = expf(g_attnlog[tid] - s_m) / s_s;
            __syncthreads();
            int col = blockIdx.x * 128 + (tid & 127);
            int seg = tid >> 7;                 // 0..7
            int i0 = seg * 17, i1 = min(AROWS, i0 + 17);
            float p = 0.f;
            for (int i = i0; i < i1; i++) p = fmaf(s_w[i], g_encout[i * H + col], p);
            s_ps[tid] = p;
            __syncthreads();
            if (tid < 128) {
                float c = 0.f;
#pragma unroll
                for (int s2 = 0; s2 < 8; s2++) c += s_ps[s2 * 128 + tid];
                g_ctx[blockIdx.x * 128 + tid] = c;
            }
        }
        grid_sync();

        // --- D3: x = relu(comb_W @ [emb; ctx] + comb_b) ---
        for (int i = WGID; i < H; i += NW) {
            const float* w = comb_W + i * (2 * H);
            float s = dot1536(w, emb, lane) + dot1536(w + H, g_ctx, lane);
            s = wredu(s);
            if (lane == 0) g_x[i] = fmaxf(0.f, s + comb_b[i]);
        }
        grid_sync();

        // --- D4: gi = dec_Wih @ x, gates -> h' ---
        {
            float* hnew = g_h[cur ^ 1];
            for (int j = WGID; j < H; j += NW) {
                float ar = wredu(dot1536(dec_Wih + j * H,           g_x, lane));
                float az = wredu(dot1536(dec_Wih + (H + j) * H,     g_x, lane));
                float an = wredu(dot1536(dec_Wih + (2 * H + j) * H, g_x, lane));
                if (lane == 0) {
                    float r = sigm((ar + dec_bih[j])         + g_gh[j]);
                    float z = sigm((az + dec_bih[H + j])     + g_gh[H + j]);
                    float n = tanhf((an + dec_bih[2 * H + j]) + r * g_gh[2 * H + j]);
                    hnew[j] = (1.f - z) * n + z * hold[j];
                }
            }
        }
        grid_sync();

        // --- D5: output logits o = out_W @ h' + out_b ---
        {
            const float* hnew = g_h[cur ^ 1];
            for (int v = WGID; v < HV; v += NW) {
                float s = wredu(dot1536(out_W + v * H, hnew, lane));
                if (lane == 0) g_o[v] = s + out_b[v];
            }
        }
        grid_sync();
        cur ^= 1;
    }

    // ---- epilogue: emit final row (ML-1) ----
    if (blockIdx.x == 0) {
        if (tid == 0) {
            float m = -1e30f; int am = 0;
            for (int v = 0; v < HV; v++) {
                float ov = g_o[v];
                if (ov > m) { m = ov; am = v; }
            }
            float s = 0.f;
            for (int v = 0; v < HV; v++) s += expf(g_o[v] - m);
            s_lse = m + logf(s);
            s_tok = am;
        }
        __syncthreads();
        if (tid < HV) out[(ML - 1) * HV + tid] = g_o[tid] - s_lse;
        if (tid == HV && write_tok) out[ML * HV + (ML - 1)] = (float)s_tok;
    }
}

// ---------------- launch ----------------
extern "C" void kernel_launch(void* const* d_in, const int* in_sizes, int n_in,
                              void* d_out, int out_size) {
    const int*   input   = (const int*)  d_in[0];
    const int    L       = in_sizes[0];
    // d_in[1] = max_length scalar (compile-time ML=128)
    const float* emb_enc = (const float*)d_in[2];
    const float* enc_Wih = (const float*)d_in[3];
    const float* enc_Whh = (const float*)d_in[4];
    const float* enc_bih = (const float*)d_in[5];
    const float* enc_bhh = (const float*)d_in[6];
    const float* emb_dec = (const float*)d_in[7];
    const float* attn_W  = (const float*)d_in[8];
    const float* attn_b  = (const float*)d_in[9];
    const float* comb_W  = (const float*)d_in[10];
    const float* comb_b  = (const float*)d_in[11];
    const float* dec_Wih = (const float*)d_in[12];
    const float* dec_Whh = (const float*)d_in[13];
    const float* dec_bih = (const float*)d_in[14];
    const float* dec_bhh = (const float*)d_in[15];
    const float* out_W   = (const float*)d_in[16];
    const float* out_b   = (const float*)d_in[17];

    int write_tok = (out_size >= ML * HV + ML) ? 1 : 0;

    seq2seq_kernel<<<GRID, BLOCK>>>(input, L, emb_enc,
                                    enc_Wih, enc_Whh, enc_bih, enc_bhh,
                                    emb_dec, attn_W, attn_b, comb_W, comb_b,
                                    dec_Wih, dec_Whh, dec_bih, dec_bhh,
                                    out_W, out_b,
                                    (float*)d_out, write_tok);
}

// round 5
// speedup vs baseline: 1.4600x; 1.4600x over previous
#include <cuda_runtime.h>
#include <math.h>

// Problem constants
#define H     1536
#define H3    4608          // 3*H
#define HV    128           // vocab
#define ML    128           // max_length
#define AROWS 129           // ML+1 attention rows
#define MPAD  132           // padded row stride for 129-wide matrices
#define GRID  148
#define BLOCK 1024
#define NW_TOT (GRID * (BLOCK / 32))   // 4736 warps

// ---------------- device scratch (no allocations allowed) ----------------
__device__ __align__(16) float g_h[2][H];             // ping-pong hidden state
__device__ __align__(16) float g_encout[AROWS * H];   // encoder_outputs (129 x 1536)
__device__ __align__(16) float g_gh[H3];              // dec_Whh @ h + bhh
__device__ __align__(16) float g_attnh[AROWS];        // attn h-half logits
__device__ __align__(16) float g_o[HV];               // output logits
__device__ __align__(16) float g_x[H];                // relu(comb) input to dec GRU
__device__ __align__(16) float g_M[H * MPAD];         // comb_W_ctx @ encout^T  (1536 x 129)
__device__ __align__(16) float g_attE[HV * MPAD];     // attn_W_emb @ emb_dec^T + attn_b (per vocab)
__device__ __align__(16) float g_combE[HV * H];       // comb_W_emb @ emb_dec^T + comb_b (per vocab)
__device__ unsigned g_bar;                            // grid barrier (monotonic)

// ---------------- grid-wide barrier (all 148 CTAs resident: 1 CTA/SM) ----
__device__ __forceinline__ void grid_sync() {
    __syncthreads();
    if (threadIdx.x == 0) {
        __threadfence();
        unsigned nb  = gridDim.x;
        unsigned old = atomicAdd(&g_bar, 1u);
        unsigned target = old - (old % nb) + nb;   // next multiple of nb
        while ((int)(*(volatile unsigned*)&g_bar - target) < 0) { }
        __threadfence();
    }
    __syncthreads();
}

// ---------------- warp helpers ----------------
__device__ __forceinline__ float wredu(float v) {
#pragma unroll
    for (int o = 16; o; o >>= 1) v += __shfl_xor_sync(0xffffffffu, v, o);
    return v;
}

// argmax with first-index tie-break (matches jnp.argmax)
__device__ __forceinline__ void wargmax(float& m, int& am) {
#pragma unroll
    for (int o = 16; o; o >>= 1) {
        float m2 = __shfl_xor_sync(0xffffffffu, m, o);
        int   a2 = __shfl_xor_sync(0xffffffffu, am, o);
        if (m2 > m || (m2 == m && a2 < am)) { m = m2; am = a2; }
    }
}

// per-lane partial dot of a 1536-length row with a 1536-length vector
__device__ __forceinline__ float dot1536(const float* __restrict__ w,
                                         const float* __restrict__ x, int lane) {
    const float4* w4 = (const float4*)w;
    const float4* x4 = (const float4*)x;
    float s = 0.f;
#pragma unroll 4
    for (int i = 0; i < 12; i++) {
        float4 a = w4[lane + 32 * i];
        float4 b = x4[lane + 32 * i];
        s = fmaf(a.x, b.x, s);
        s = fmaf(a.y, b.y, s);
        s = fmaf(a.z, b.z, s);
        s = fmaf(a.w, b.w, s);
    }
    return s;
}

// 4 dots sharing one weight row (for precompute GEMMs)
__device__ __forceinline__ void dot1536x4(const float* __restrict__ w,
                                          const float* __restrict__ x0,
                                          const float* __restrict__ x1,
                                          const float* __restrict__ x2,
                                          const float* __restrict__ x3,
                                          int lane, float* r) {
    const float4* w4 = (const float4*)w;
    const float4* a0 = (const float4*)x0;
    const float4* a1 = (const float4*)x1;
    const float4* a2 = (const float4*)x2;
    const float4* a3 = (const float4*)x3;
    float s0 = 0.f, s1 = 0.f, s2 = 0.f, s3 = 0.f;
#pragma unroll 4
    for (int i = 0; i < 12; i++) {
        float4 a = w4[lane + 32 * i];
        float4 b;
        b = a0[lane + 32 * i];
        s0 = fmaf(a.x, b.x, s0); s0 = fmaf(a.y, b.y, s0);
        s0 = fmaf(a.z, b.z, s0); s0 = fmaf(a.w, b.w, s0);
        b = a1[lane + 32 * i];
        s1 = fmaf(a.x, b.x, s1); s1 = fmaf(a.y, b.y, s1);
        s1 = fmaf(a.z, b.z, s1); s1 = fmaf(a.w, b.w, s1);
        b = a2[lane + 32 * i];
        s2 = fmaf(a.x, b.x, s2); s2 = fmaf(a.y, b.y, s2);
        s2 = fmaf(a.z, b.z, s2); s2 = fmaf(a.w, b.w, s2);
        b = a3[lane + 32 * i];
        s3 = fmaf(a.x, b.x, s3); s3 = fmaf(a.y, b.y, s3);
        s3 = fmaf(a.z, b.z, s3); s3 = fmaf(a.w, b.w, s3);
    }
    r[0] = s0; r[1] = s1; r[2] = s2; r[3] = s3;
}

__device__ __forceinline__ float sigm(float x) { return 1.f / (1.f + expf(-x)); }

// ---------------- persistent kernel ----------------
__global__ __launch_bounds__(BLOCK, 1)
void seq2seq_kernel(const int* __restrict__ input, int L,
                    const float* __restrict__ emb_enc,
                    const float* __restrict__ enc_Wih, const float* __restrict__ enc_Whh,
                    const float* __restrict__ enc_bih, const float* __restrict__ enc_bhh,
                    const float* __restrict__ emb_dec,
                    const float* __restrict__ attn_W, const float* __restrict__ attn_b,
                    const float* __restrict__ comb_W, const float* __restrict__ comb_b,
                    const float* __restrict__ dec_Wih, const float* __restrict__ dec_Whh,
                    const float* __restrict__ dec_bih, const float* __restrict__ dec_bhh,
                    const float* __restrict__ out_W, const float* __restrict__ out_b,
                    float* __restrict__ out, int write_tok)
{
    const int tid  = threadIdx.x;
    const int lane = tid & 31;
    const int wid  = tid >> 5;
    // interleave warp ids across blocks so every phase keeps all SMs busy
    const int WGID = wid * gridDim.x + blockIdx.x;
    const int NW   = gridDim.x * (blockDim.x >> 5);

    __shared__ float s_w[AROWS];     // unnormalized softmax weights
    __shared__ float s_S, s_lse;
    __shared__ int   s_tok;

    // ---- init: zero h0 and the unused tail rows of encoder_outputs ----
    {
        int gt = blockIdx.x * blockDim.x + tid;
        int NT = gridDim.x * blockDim.x;
        for (int i = gt; i < H; i += NT) g_h[0][i] = 0.f;
        for (int i = L * H + gt; i < AROWS * H; i += NT) g_encout[i] = 0.f;
    }

    // ---- P_E precompute (once): emb-half GEMMs for attn and comb + bias fold ----
    // virtual rows: [0,AROWS) -> attn_W emb-half, [AROWS,AROWS+H) -> comb_W emb-half
    {
        int b  = blockIdx.x;
        int r0 = b * 11 + min(b, 37);
        int nr = 11 + (b < 37 ? 1 : 0);       // 37*12 + 111*11 = 1665 rows
        for (int u = wid; u < nr * 32; u += 32) {
            int lr = u >> 5;
            int vc = (u & 31) << 2;           // vocab chunk base (0..124)
            int r  = r0 + lr;
            const float* w; float bias;
            if (r < AROWS) { w = attn_W + r * (2 * H); bias = attn_b[r]; }
            else           { w = comb_W + (r - AROWS) * (2 * H); bias = comb_b[r - AROWS]; }
            float s[4];
            dot1536x4(w, emb_dec + vc * H, emb_dec + (vc + 1) * H,
                         emb_dec + (vc + 2) * H, emb_dec + (vc + 3) * H, lane, s);
#pragma unroll
            for (int q = 0; q < 4; q++) s[q] = wredu(s[q]);
            if (lane == 0) {
#pragma unroll
                for (int q = 0; q < 4; q++) {
                    if (r < AROWS) g_attE[(vc + q) * MPAD + r] = s[q] + bias;
                    else           g_combE[(vc + q) * H + (r - AROWS)] = s[q] + bias;
                }
            }
        }
    }
    grid_sync();

    int cur = 0;

    // =========================== ENCODER ===========================
    for (int t = 0; t < L; t++) {
        const float* x    = emb_enc + input[t] * H;
        const float* hold = g_h[cur];
        float*       hnew = g_h[cur ^ 1];

        for (int j = WGID; j < H; j += NW) {
            float ar = dot1536(enc_Wih + j * H,            x, lane);
            float az = dot1536(enc_Wih + (H + j) * H,      x, lane);
            float an = dot1536(enc_Wih + (2 * H + j) * H,  x, lane);
            float br = dot1536(enc_Whh + j * H,            hold, lane);
            float bz = dot1536(enc_Whh + (H + j) * H,      hold, lane);
            float bn = dot1536(enc_Whh + (2 * H + j) * H,  hold, lane);
            float rp  = wredu(ar + br);
            float zp  = wredu(az + bz);
            float anr = wredu(an);
            float bnr = wredu(bn);
            if (lane == 0) {
                float r  = sigm(rp + enc_bih[j] + enc_bhh[j]);
                float z  = sigm(zp + enc_bih[H + j] + enc_bhh[H + j]);
                float n  = tanhf(anr + enc_bih[2 * H + j] + r * (bnr + enc_bhh[2 * H + j]));
                float hv = (1.f - z) * n + z * hold[j];
                hnew[j] = hv;
                g_encout[t * H + j] = hv;
            }
        }
        grid_sync();
        cur ^= 1;
    }

    // ---- P_M precompute (once): M[i][k] = comb_W_ctx[i,:] . encout[k,:] ----
    {
        int b  = blockIdx.x;
        int r0 = b * 10 + min(b, 56);
        int nr = 10 + (b < 56 ? 1 : 0);       // 56*11 + 92*10 = 1536 rows
        for (int u = wid; u < nr * 33; u += 32) {
            int lr = u / 33;
            int kc = (u % 33) * 4;            // 0..128
            int i  = r0 + lr;
            const float* w = comb_W + i * (2 * H) + H;
            int k0 = min(kc,     AROWS - 1);
            int k1 = min(kc + 1, AROWS - 1);
            int k2 = min(kc + 2, AROWS - 1);
            int k3 = min(kc + 3, AROWS - 1);
            float s[4];
            dot1536x4(w, g_encout + k0 * H, g_encout + k1 * H,
                         g_encout + k2 * H, g_encout + k3 * H, lane, s);
#pragma unroll
            for (int q = 0; q < 4; q++) s[q] = wredu(s[q]);
            if (lane == 0) {
#pragma unroll
                for (int q = 0; q < 4; q++) {
                    int k = kc + q;
                    if (k < AROWS) g_M[i * MPAD + k] = s[q];
                }
            }
        }
    }
    grid_sync();

    // =========================== DECODER ===========================
    for (int t = 0; t < ML; t++) {
        const float* h = g_h[cur];

        // --- P1: gh = Whh.h+bhh (4608) || out logits (128) || attn_h (129) ---
        for (int task = WGID; task < H3 + HV + AROWS; task += NW) {
            if (task < H3) {
                float s = wredu(dot1536(dec_Whh + task * H, h, lane));
                if (lane == 0) g_gh[task] = s + dec_bhh[task];
            } else if (task < H3 + HV) {
                int v = task - H3;
                float s = wredu(dot1536(out_W + v * H, h, lane));
                if (lane == 0) g_o[v] = s + out_b[v];
            } else {
                int k = task - H3 - HV;
                float s = wredu(dot1536(attn_W + k * (2 * H) + H, h, lane));
                if (lane == 0) g_attnh[k] = s;
            }
        }
        grid_sync();

        // --- P2: token select, emit row t-1, softmax, x rows ---
        if (wid == 0) {
            int tok; float lse;
            if (t == 0) { tok = 0; lse = 0.f; }
            else {
                float m = -1e30f; int am = HV;
                for (int v = lane; v < HV; v += 32) {
                    float ov = g_o[v];
                    if (ov > m) { m = ov; am = v; }
                }
                wargmax(m, am);
                float e = 0.f;
                for (int v = lane; v < HV; v += 32) e += expf(g_o[v] - m);
                e = wredu(e);
                lse = m + logf(e);
                tok = am;
            }
            if (lane == 0) { s_tok = tok; s_lse = lse; }
        }
        __syncthreads();
        const int tok = s_tok;
        if (t > 0 && blockIdx.x == 0 && wid == 1) {
            for (int v = lane; v < HV; v += 32) out[(t - 1) * HV + v] = g_o[v] - s_lse;
            if (lane == 0 && write_tok) out[ML * HV + (t - 1)] = (float)tok;
        }
        if (wid == 0) {
            const float* aE = g_attE + tok * MPAD;
            float m = -1e30f;
            for (int k = lane; k < AROWS; k += 32) m = fmaxf(m, aE[k] + g_attnh[k]);
#pragma unroll
            for (int o = 16; o; o >>= 1) m = fmaxf(m, __shfl_xor_sync(0xffffffffu, m, o));
            float ssum = 0.f;
            for (int k = lane; k < AROWS; k += 32) {
                float e = expf(aE[k] + g_attnh[k] - m);
                s_w[k] = e;
                ssum += e;
            }
            ssum = wredu(ssum);
            if (lane == 0) s_S = ssum;
        }
        __syncthreads();
        {
            const float invS = 1.f / s_S;
            const float* cE = g_combE + tok * H;
            for (int i = WGID; i < H; i += NW) {
                const float* Mr = g_M + i * MPAD;
                float s = 0.f;
                for (int k = lane; k < AROWS; k += 32) s = fmaf(s_w[k], Mr[k], s);
                s = wredu(s);
                if (lane == 0) g_x[i] = fmaxf(0.f, cE[i] + s * invS);
            }
        }
        grid_sync();

        // --- P3: gi = dec_Wih @ x, gates -> h' ---
        {
            const float* hold = h;
            float* hnew = g_h[cur ^ 1];
            for (int j = WGID; j < H; j += NW) {
                float ar = wredu(dot1536(dec_Wih + j * H,           g_x, lane));
                float az = wredu(dot1536(dec_Wih + (H + j) * H,     g_x, lane));
                float an = wredu(dot1536(dec_Wih + (2 * H + j) * H, g_x, lane));
                if (lane == 0) {
                    float r = sigm(ar + dec_bih[j]          + g_gh[j]);
                    float z = sigm(az + dec_bih[H + j]      + g_gh[H + j]);
                    float n = tanhf(an + dec_bih[2 * H + j] + r * g_gh[2 * H + j]);
                    hnew[j] = (1.f - z) * n + z * hold[j];
                }
            }
        }
        grid_sync();
        cur ^= 1;
    }

    // ---- final logits for row ML-1 ----
    {
        const float* hf = g_h[cur];
        for (int v = WGID; v < HV; v += NW) {
            float s = wredu(dot1536(out_W + v * H, hf, lane));
            if (lane == 0) g_o[v] = s + out_b[v];
        }
    }
    grid_sync();

    if (blockIdx.x == 0 && wid == 0) {
        float m = -1e30f; int am = HV;
        for (int v = lane; v < HV; v += 32) {
            float ov = g_o[v];
            if (ov > m) { m = ov; am = v; }
        }
        wargmax(m, am);
        float e = 0.f;
        for (int v = lane; v < HV; v += 32) e += expf(g_o[v] - m);
        e = wredu(e);
        float lse = m + logf(e);
        for (int v = lane; v < HV; v += 32) out[(ML - 1) * HV + v] = g_o[v] - lse;
        if (lane == 0 && write_tok) out[ML * HV + (ML - 1)] = (float)am;
    }
}

// ---------------- launch ----------------
extern "C" void kernel_launch(void* const* d_in, const int* in_sizes, int n_in,
                              void* d_out, int out_size) {
    const int*   input   = (const int*)  d_in[0];
    const int    L       = in_sizes[0];
    // d_in[1] = max_length scalar (compile-time ML=128)
    const float* emb_enc = (const float*)d_in[2];
    const float* enc_Wih = (const float*)d_in[3];
    const float* enc_Whh = (const float*)d_in[4];
    const float* enc_bih = (const float*)d_in[5];
    const float* enc_bhh = (const float*)d_in[6];
    const float* emb_dec = (const float*)d_in[7];
    const float* attn_W  = (const float*)d_in[8];
    const float* attn_b  = (const float*)d_in[9];
    const float* comb_W  = (const float*)d_in[10];
    const float* comb_b  = (const float*)d_in[11];
    const float* dec_Wih = (const float*)d_in[12];
    const float* dec_Whh = (const float*)d_in[13];
    const float* dec_bih = (const float*)d_in[14];
    const float* dec_bhh = (const float*)d_in[15];
    const float* out_W   = (const float*)d_in[16];
    const float* out_b   = (const float*)d_in[17];

    int write_tok = (out_size >= ML * HV + ML) ? 1 : 0;

    seq2seq_kernel<<<GRID, BLOCK>>>(input, L, emb_enc,
                                    enc_Wih, enc_Whh, enc_bih, enc_bhh,
                                    emb_dec, attn_W, attn_b, comb_W, comb_b,
                                    dec_Wih, dec_Whh, dec_bih, dec_bhh,
                                    out_W, out_b,
                                    (float*)d_out, write_tok);
}